// round 7
// baseline (speedup 1.0000x reference)
#include <cuda_runtime.h>
#include <math.h>

#define B 128
#define T 1024
#define H 256
#define G4 1024   // 4*H

// ------------------- device scratch (static, zero-initialized) -------------------
__device__ float g_xp[(size_t)2 * T * B * G4];     // x@Wih.T + b, rows reordered (4*h+gate), [d][t][b][1024]
__device__ float g_hstore[(size_t)2 * T * B * H];  // recorded h, [d][t][b][h]
__device__ float g_WTT[2 * G4 * H];                // Whh reordered rows, row-major: [d][r'][k]
__device__ float g_outWT[512 * 32];                // out_W transposed: [k][j]
__device__ float g_hbuf[2 * 2 * B * H];            // ping-pong h state: [parity][d][b][h]
__device__ float g_c[2 * B * H];                   // cell state: [d][b][h]
__device__ float g_af[B * 32];                     // addr_feat
__device__ float g_scores[B * T];
__device__ int   g_cnt[16];                        // per-(dir,btile) step counters

__device__ __forceinline__ void ffma2(unsigned long long& d,
                                      unsigned long long a,
                                      unsigned long long b) {
    asm("fma.rn.f32x2 %0, %1, %2, %0;" : "+l"(d) : "l"(a), "l"(b));
}
__device__ __forceinline__ float sigmoid_fast(float x) {
    float e = __expf(-x);
    float r;
    asm("rcp.approx.f32 %0, %1;" : "=f"(r) : "f"(1.0f + e));
    return r;
}
__device__ __forceinline__ float tanh_fast(float x) {
    float r;
    asm("tanh.approx.f32 %0, %1;" : "=f"(r) : "f"(x));
    return r;
}
__device__ __forceinline__ void cnt_release(int* cnt) {
    asm volatile("red.release.gpu.global.add.s32 [%0], %1;"
                 :: "l"(cnt), "r"(1) : "memory");
}
__device__ __forceinline__ void cnt_poll(int* cnt, int target) {
    int v;
    do {
        asm volatile("ld.acquire.gpu.global.s32 %0, [%1];"
                     : "=r"(v) : "l"(cnt) : "memory");
    } while (v < target);
}

// ------------------- clear state (per replay) -------------------
__global__ void clear_kernel() {
    int i = blockIdx.x * 256 + threadIdx.x;
    if (i < 2 * 2 * B * H) g_hbuf[i] = 0.0f;
    if (i < 2 * B * H)     g_c[i]    = 0.0f;
    if (i < 16)            g_cnt[i]  = 0;
}

// ------------------- weight prep: gate-interleaved rows, row-major -------------------
__global__ void prep_kernel(const float* __restrict__ Whh_f,
                            const float* __restrict__ Whh_b,
                            const float* __restrict__ out_W) {
    int idx = blockIdx.x * 256 + threadIdx.x;
    if (idx < 2 * G4 * H) {
        int k  = idx & 255;
        int rp = (idx >> 8) & 1023;   // reordered row r' = 4*jh + g
        int d  = idx >> 18;
        int g  = rp & 3, jh = rp >> 2;
        const float* Whh = d ? Whh_b : Whh_f;
        g_WTT[idx] = Whh[(g * 256 + jh) * H + k];
    }
    if (idx < 512 * 32) {
        int k = idx >> 5, j = idx & 31;
        g_outWT[idx] = out_W[j * 512 + k];
    }
}

// ------------------- addr_feat -------------------
__global__ void addr_kernel(const float* __restrict__ addr,
                            const int*   __restrict__ addr_type,
                            const float* __restrict__ poi_emb,
                            const float* __restrict__ addr_W,
                            const float* __restrict__ addr_b) {
    int b = threadIdx.x;  // 128
    float inp[4];
    inp[0] = addr[b];
    int at = addr_type[b];
    inp[1] = poi_emb[at * 3 + 0];
    inp[2] = poi_emb[at * 3 + 1];
    inp[3] = poi_emb[at * 3 + 2];
    for (int j = 0; j < 32; j++) {
        float a = addr_b[j];
        #pragma unroll
        for (int f = 0; f < 4; f++) a += addr_W[j * 4 + f] * inp[f];
        g_af[b * 32 + j] = a;
    }
}

// ------------------- xp = loc_seq @ Wih.T + b (reordered rows), active (b,t) only -------------------
__global__ void __launch_bounds__(256) xp_kernel(
    const float* __restrict__ loc_dense, const float* __restrict__ time_dist,
    const int* __restrict__ len, const float* __restrict__ time_W,
    const float* __restrict__ time_b,
    const float* __restrict__ Wih_f, const float* __restrict__ b_f,
    const float* __restrict__ Wih_b, const float* __restrict__ b_b) {
    int b = blockIdx.y, d = blockIdx.z;
    int t0 = blockIdx.x * 32;
    int n = len[b];
    if (t0 >= n) return;
    const float* Wih  = d ? Wih_b : Wih_f;
    const float* bias = d ? b_b  : b_f;

    __shared__ float loc19[32][19];
    int tid = threadIdx.x;
    for (int i = tid; i < 32 * 16; i += 256) {
        int tt = i >> 4, f = i & 15;
        loc19[tt][f] = loc_dense[((size_t)b * T + t0 + tt) * 16 + f];
    }
    if (tid < 96) {
        int tt = tid / 3, e = tid % 3;
        float acc = time_b[e];
        const float* tdp = &time_dist[((size_t)b * T + t0 + tt) * 8];
        #pragma unroll
        for (int f = 0; f < 8; f++) acc += time_W[e * 8 + f] * tdp[f];
        loc19[tt][16 + e] = acc;
    }
    __syncthreads();

    int j = tid;  // h index 0..255; owns reordered rows 4j..4j+3
    float w[4][19], bz[4];
    #pragma unroll
    for (int g = 0; g < 4; g++) {
        int orig = g * 256 + j;
        bz[g] = bias[orig];
        #pragma unroll
        for (int f = 0; f < 19; f++) w[g][f] = Wih[orig * 19 + f];
    }
    int tmax = min(32, n - t0);
    for (int tt = 0; tt < tmax; tt++) {
        float accs[4];
        #pragma unroll
        for (int g = 0; g < 4; g++) {
            float a = bz[g];
            #pragma unroll
            for (int f = 0; f < 19; f++) a += w[g][f] * loc19[tt][f];
            accs[g] = a;
        }
        float4 out4 = make_float4(accs[0], accs[1], accs[2], accs[3]);
        *(float4*)&g_xp[(((size_t)d * T + t0 + tt) * B + b) * G4 + j * 4] = out4;
    }
}

// ------------------- persistent bidirectional LSTM, dual-chain interleaved -------------------
// Grid (16 gx, 8 gy) = 128 CTAs co-resident. Each CTA: 64 f-rows + 64 b-rows x 16 batches.
// Both dirs' recurrences interleave in one CTA so each chain's sync latency hides
// under the other chain's GEMM. Groups = 16 CTAs per (dir, gy); counter barrier.
// Thread: tx = local row (0..63), ty = batch half, kz = k quarter (64 k each).
__device__ __forceinline__ void lstm_phase(
    int dirIdx, int s, int i, int gx, int b0, int tid,
    const float* sWT, const float* hT, float* pre, const int* __restrict__ len) {
    int tx = tid & 63;
    int q  = tid >> 6;
    int ty = q & 1;
    int kz = q >> 1;
    int pout = (i & 1) ^ 1;
    int g0 = gx * 64;

    float xpre[8];
    if (kz == 0) {
        size_t xb = (((size_t)dirIdx * T + s) * B + b0 + ty * 8) * G4 + g0 + tx;
        #pragma unroll
        for (int j = 0; j < 8; j++) xpre[j] = g_xp[xb + (size_t)j * G4];
    }

    unsigned long long acc[8];
    #pragma unroll
    for (int j = 0; j < 8; j++) acc[j] = 0ULL;
    {
        const float* wrow  = &sWT[(dirIdx * 64 + tx) * 260 + kz * 64];
        const float* hbase = &hT[(ty * 8) * 260 + kz * 64];
        #pragma unroll 4
        for (int k = 0; k < 64; k += 4) {
            ulonglong2 w2 = *(const ulonglong2*)(wrow + k);
            #pragma unroll
            for (int j = 0; j < 8; j++) {
                ulonglong2 h2 = *(const ulonglong2*)(hbase + j * 260 + k);
                ffma2(acc[j], w2.x, h2.x);
                ffma2(acc[j], w2.y, h2.y);
            }
        }
    }
    #pragma unroll
    for (int j = 0; j < 8; j++) {
        float2 f2 = *reinterpret_cast<float2*>(&acc[j]);
        float v = f2.x + f2.y;
        if (kz == 0) v += xpre[j];
        pre[(kz * 16 + ty * 8 + j) * 68 + tx] = v;
    }
    __syncthreads();

    // epilogue: 16 h x 16 b = 256 cells, tid < 256
    if (tid < 256) {
        int hl = tid & 15, b2 = tid >> 4;
        int b  = b0 + b2;
        int hglob = gx * 16 + hl;
        size_t ho = ((size_t)(pout * 2 + dirIdx) * B + b) * H + hglob;
        float hn;
        if (s < len[b]) {
            float4 gA = *(const float4*)&pre[(0 * 16 + b2) * 68 + 4 * hl];
            float4 gB = *(const float4*)&pre[(1 * 16 + b2) * 68 + 4 * hl];
            float4 gC = *(const float4*)&pre[(2 * 16 + b2) * 68 + 4 * hl];
            float4 gD = *(const float4*)&pre[(3 * 16 + b2) * 68 + 4 * hl];
            float gi = gA.x + gB.x + gC.x + gD.x;
            float gf = gA.y + gB.y + gC.y + gD.y;
            float gg = gA.z + gB.z + gC.z + gD.z;
            float go = gA.w + gB.w + gC.w + gD.w;
            size_t ci = ((size_t)dirIdx * B + b) * H + hglob;
            float cold = g_c[ci];
            float cn = sigmoid_fast(gf) * cold + sigmoid_fast(gi) * tanh_fast(gg);
            hn = sigmoid_fast(go) * tanh_fast(cn);
            g_c[ci] = cn;
            g_hstore[(((size_t)dirIdx * T + s) * B + b) * H + hglob] = hn;
        } else {
            hn = hT[b2 * 260 + hglob];  // carry forward
        }
        g_hbuf[ho] = hn;
    }
    __syncthreads();
}

__global__ void __launch_bounds__(512, 1) lstm_kernel(const int* __restrict__ len) {
    extern __shared__ float smem[];
    float* sWT  = smem;                    // [128][260]  (64 f-rows, 64 b-rows)
    float* hT_f = smem + 128 * 260;        // [16][260]
    float* hT_b = hT_f + 16 * 260;         // [16][260]
    float* pre  = hT_b + 16 * 260;         // [64][68]

    int gx = blockIdx.x, gy = blockIdx.y;
    int tid = threadIdx.x;
    int b0 = gy * 16;
    int nloc = len[b0];                    // sorted descending
    int* cnt_f = &g_cnt[gy];
    int* cnt_b = &g_cnt[8 + gy];

    // resident weights for both dirs
    for (int e = tid; e < 128 * 256; e += 512) {
        int row = e >> 8, k = e & 255;
        int d = row >> 6, r = row & 63;
        sWT[row * 260 + k] = g_WTT[((size_t)d * G4 + gx * 64 + r) * 256 + k];
    }
    for (int e = tid; e < 2 * 16 * 260; e += 512) hT_f[e] = 0.0f;
    __syncthreads();

    for (int i = 0; i < nloc; i++) {
        int pin = i & 1;

        // ---- chain F, step i (hT_f holds h_f(i-1)) ----
        lstm_phase(0, i, i, gx, b0, tid, sWT, hT_f, pre, len);
        if (tid == 0) cnt_release(cnt_f);

        // ---- stage h_b(i-1): peers released it one phase ago -> poll ~free ----
        if (i > 0) cnt_poll(cnt_b, 16 * i);
        {
            const float* hg = &g_hbuf[((size_t)(pin * 2 + 1) * B + b0) * H];
            #pragma unroll
            for (int p = 0; p < 2; p++) {
                int idx = tid + 512 * p;
                int b = idx >> 6, k4 = (idx & 63) * 4;
                float4 v4 = __ldcg((const float4*)&hg[b * H + k4]);
                *(float4*)&hT_b[b * 260 + k4] = v4;
            }
        }
        __syncthreads();

        // ---- chain B, step i ----
        lstm_phase(1, nloc - 1 - i, i, gx, b0, tid, sWT, hT_b, pre, len);
        if (tid == 0) cnt_release(cnt_b);

        // ---- stage h_f(i): released during our B phase -> poll ~free ----
        if (i + 1 < nloc) {
            cnt_poll(cnt_f, 16 * (i + 1));
            const float* hg = &g_hbuf[((size_t)(((i + 1) & 1) * 2 + 0) * B + b0) * H];
            #pragma unroll
            for (int p = 0; p < 2; p++) {
                int idx = tid + 512 * p;
                int b = idx >> 6, k4 = (idx & 63) * 4;
                float4 v4 = __ldcg((const float4*)&hg[b * H + k4]);
                *(float4*)&hT_f[b * 260 + k4] = v4;
            }
            __syncthreads();
        }
    }
}

// ------------------- scores: comb_W . tanh(out_W @ [hf;hb] + addr_feat) -------------------
__global__ void __launch_bounds__(256) score_kernel(const int* __restrict__ len,
                                                    const float* __restrict__ comb_W) {
    int b = blockIdx.y;
    int t0 = blockIdx.x * 8;
    int n = len[b];
    if (t0 >= n) return;
    int w = threadIdx.x >> 5, lane = threadIdx.x & 31;
    int t = t0 + w;
    if (t >= n) return;
    float a0 = g_af[b * 32 + lane], a1 = 0.f, a2 = 0.f, a3 = 0.f;
    const float* hf = &g_hstore[(((size_t)0 * T + t) * B + b) * H];
    const float* hb = &g_hstore[(((size_t)1 * T + t) * B + b) * H];
    #pragma unroll 8
    for (int k = 0; k < 256; k += 4) {
        float4 h4 = *(const float4*)&hf[k];
        a0 = fmaf(g_outWT[(k + 0) * 32 + lane], h4.x, a0);
        a1 = fmaf(g_outWT[(k + 1) * 32 + lane], h4.y, a1);
        a2 = fmaf(g_outWT[(k + 2) * 32 + lane], h4.z, a2);
        a3 = fmaf(g_outWT[(k + 3) * 32 + lane], h4.w, a3);
    }
    #pragma unroll 8
    for (int k = 0; k < 256; k += 4) {
        float4 h4 = *(const float4*)&hb[k];
        a0 = fmaf(g_outWT[(256 + k + 0) * 32 + lane], h4.x, a0);
        a1 = fmaf(g_outWT[(256 + k + 1) * 32 + lane], h4.y, a1);
        a2 = fmaf(g_outWT[(256 + k + 2) * 32 + lane], h4.z, a2);
        a3 = fmaf(g_outWT[(256 + k + 3) * 32 + lane], h4.w, a3);
    }
    float v = tanhf(a0 + a1 + a2 + a3) * comb_W[lane];
    #pragma unroll
    for (int off = 16; off; off >>= 1) v += __shfl_down_sync(0xffffffffu, v, off);
    if (lane == 0) g_scores[b * T + t] = v;
}

// ------------------- masked log-softmax over T -------------------
__global__ void __launch_bounds__(256) softmax_kernel(const int* __restrict__ len,
                                                      float* __restrict__ out) {
    int b = blockIdx.x;
    int n = len[b];
    int tid = threadIdx.x;
    __shared__ float red[256];
    float m = -1e30f;
    for (int t = tid; t < n; t += 256) m = fmaxf(m, g_scores[b * T + t]);
    red[tid] = m; __syncthreads();
    for (int st = 128; st; st >>= 1) {
        if (tid < st) red[tid] = fmaxf(red[tid], red[tid + st]);
        __syncthreads();
    }
    m = red[0]; __syncthreads();
    float sum = 0.f;
    for (int t = tid; t < n; t += 256) sum += expf(g_scores[b * T + t] - m);
    red[tid] = sum; __syncthreads();
    for (int st = 128; st; st >>= 1) {
        if (tid < st) red[tid] += red[tid + st];
        __syncthreads();
    }
    float lse = m + logf(red[0]);
    for (int t = tid; t < T; t += 256)
        out[b * T + t] = (t < n) ? (g_scores[b * T + t] - lse) : 0.0f;
}

// ------------------- launch -------------------
extern "C" void kernel_launch(void* const* d_in, const int* in_sizes, int n_in,
                              void* d_out, int out_size) {
    (void)in_sizes; (void)n_in; (void)out_size;
    const float* addr      = (const float*)d_in[0];
    const int*   addr_type = (const int*)  d_in[1];
    const float* loc_dense = (const float*)d_in[2];
    const float* time_dist = (const float*)d_in[3];
    const int*   len       = (const int*)  d_in[4];
    const float* poi_emb   = (const float*)d_in[5];
    const float* time_W    = (const float*)d_in[6];
    const float* time_b    = (const float*)d_in[7];
    const float* addr_W    = (const float*)d_in[8];
    const float* addr_b    = (const float*)d_in[9];
    const float* Wih_f     = (const float*)d_in[10];
    const float* Whh_f     = (const float*)d_in[11];
    const float* b_f       = (const float*)d_in[12];
    const float* Wih_b     = (const float*)d_in[13];
    const float* Whh_b     = (const float*)d_in[14];
    const float* b_b       = (const float*)d_in[15];
    const float* out_W     = (const float*)d_in[16];
    const float* comb_W    = (const float*)d_in[17];
    float* out = (float*)d_out;

    static int smem_set = 0;
    const int LSTM_SMEM = (128 * 260 + 2 * 16 * 260 + 64 * 68) * 4;  // 183808 B
    if (!smem_set) {
        cudaFuncSetAttribute(lstm_kernel,
                             cudaFuncAttributeMaxDynamicSharedMemorySize, LSTM_SMEM);
        smem_set = 1;
    }

    clear_kernel<<<512, 256>>>();
    addr_kernel<<<1, 128>>>(addr, addr_type, poi_emb, addr_W, addr_b);
    prep_kernel<<<2048, 256>>>(Whh_f, Whh_b, out_W);
    xp_kernel<<<dim3(32, 128, 2), 256>>>(loc_dense, time_dist, len, time_W, time_b,
                                         Wih_f, b_f, Wih_b, b_b);
    lstm_kernel<<<dim3(16, 8, 1), 512, LSTM_SMEM>>>(len);
    score_kernel<<<dim3(128, 128), 256>>>(len, comb_W);
    softmax_kernel<<<128, 256>>>(len, out);
}

// round 8
// speedup vs baseline: 1.3247x; 1.3247x over previous
#include <cuda_runtime.h>
#include <math.h>

#define B 128
#define T 1024
#define H 256
#define G4 1024   // 4*H

// ------------------- device scratch (static) -------------------
__device__ float g_xp[(size_t)2 * T * B * G4];     // x@Wih.T + b, rows reordered (4*h+gate), [d][t][b][1024]
__device__ float g_hstore[(size_t)2 * T * B * H];  // recorded h, [d][t][b][h]
__device__ float g_WTT[2 * G4 * H];                // Whh reordered rows, row-major: [d][r'][k]
__device__ float g_outWT[512 * 32];                // out_W transposed: [k][j]
__device__ float g_af[B * 32];                     // addr_feat
__device__ float g_scores[B * T];

__device__ __forceinline__ void ffma2(unsigned long long& d,
                                      unsigned long long a,
                                      unsigned long long b) {
    asm("fma.rn.f32x2 %0, %1, %2, %0;" : "+l"(d) : "l"(a), "l"(b));
}
__device__ __forceinline__ float sigmoid_fast(float x) {
    float e = __expf(-x);
    float r;
    asm("rcp.approx.f32 %0, %1;" : "=f"(r) : "f"(1.0f + e));
    return r;
}
__device__ __forceinline__ float tanh_fast(float x) {
    float r;
    asm("tanh.approx.f32 %0, %1;" : "=f"(r) : "f"(x));
    return r;
}

// ------------------- weight prep: gate-interleaved rows, row-major -------------------
__global__ void prep_kernel(const float* __restrict__ Whh_f,
                            const float* __restrict__ Whh_b,
                            const float* __restrict__ out_W) {
    int idx = blockIdx.x * 256 + threadIdx.x;
    if (idx < 2 * G4 * H) {
        int k  = idx & 255;
        int rp = (idx >> 8) & 1023;   // reordered row r' = 4*jh + g
        int d  = idx >> 18;
        int g  = rp & 3, jh = rp >> 2;
        const float* Whh = d ? Whh_b : Whh_f;
        g_WTT[idx] = Whh[(g * 256 + jh) * H + k];
    }
    if (idx < 512 * 32) {
        int k = idx >> 5, j = idx & 31;
        g_outWT[idx] = out_W[j * 512 + k];
    }
}

// ------------------- addr_feat -------------------
__global__ void addr_kernel(const float* __restrict__ addr,
                            const int*   __restrict__ addr_type,
                            const float* __restrict__ poi_emb,
                            const float* __restrict__ addr_W,
                            const float* __restrict__ addr_b) {
    int b = threadIdx.x;  // 128
    float inp[4];
    inp[0] = addr[b];
    int at = addr_type[b];
    inp[1] = poi_emb[at * 3 + 0];
    inp[2] = poi_emb[at * 3 + 1];
    inp[3] = poi_emb[at * 3 + 2];
    for (int j = 0; j < 32; j++) {
        float a = addr_b[j];
        #pragma unroll
        for (int f = 0; f < 4; f++) a += addr_W[j * 4 + f] * inp[f];
        g_af[b * 32 + j] = a;
    }
}

// ------------------- xp = loc_seq @ Wih.T + b (reordered rows), active (b,t) only -------------------
__global__ void __launch_bounds__(256) xp_kernel(
    const float* __restrict__ loc_dense, const float* __restrict__ time_dist,
    const int* __restrict__ len, const float* __restrict__ time_W,
    const float* __restrict__ time_b,
    const float* __restrict__ Wih_f, const float* __restrict__ b_f,
    const float* __restrict__ Wih_b, const float* __restrict__ b_b) {
    int b = blockIdx.y, d = blockIdx.z;
    int t0 = blockIdx.x * 32;
    int n = len[b];
    if (t0 >= n) return;
    const float* Wih  = d ? Wih_b : Wih_f;
    const float* bias = d ? b_b  : b_f;

    __shared__ float loc19[32][19];
    int tid = threadIdx.x;
    for (int i = tid; i < 32 * 16; i += 256) {
        int tt = i >> 4, f = i & 15;
        loc19[tt][f] = loc_dense[((size_t)b * T + t0 + tt) * 16 + f];
    }
    if (tid < 96) {
        int tt = tid / 3, e = tid % 3;
        float acc = time_b[e];
        const float* tdp = &time_dist[((size_t)b * T + t0 + tt) * 8];
        #pragma unroll
        for (int f = 0; f < 8; f++) acc += time_W[e * 8 + f] * tdp[f];
        loc19[tt][16 + e] = acc;
    }
    __syncthreads();

    int j = tid;  // h index 0..255; owns reordered rows 4j..4j+3
    float w[4][19], bz[4];
    #pragma unroll
    for (int g = 0; g < 4; g++) {
        int orig = g * 256 + j;
        bz[g] = bias[orig];
        #pragma unroll
        for (int f = 0; f < 19; f++) w[g][f] = Wih[orig * 19 + f];
    }
    int tmax = min(32, n - t0);
    for (int tt = 0; tt < tmax; tt++) {
        float accs[4];
        #pragma unroll
        for (int g = 0; g < 4; g++) {
            float a = bz[g];
            #pragma unroll
            for (int f = 0; f < 19; f++) a += w[g][f] * loc19[tt][f];
            accs[g] = a;
        }
        float4 out4 = make_float4(accs[0], accs[1], accs[2], accs[3]);
        *(float4*)&g_xp[(((size_t)d * T + t0 + tt) * B + b) * G4 + j * 4] = out4;
    }
}

// ------------------- persistent bidirectional LSTM, cluster DSMEM exchange -------------------
// Grid (8,8,2), cluster (8,1,1): cluster = 8 gate-tile CTAs sharing (btile, dir).
// CTA: 128 reordered gate rows x 16 batches; Whh tile resident in smem; c,h in regs.
// h exchange: epilogue DSMEM-broadcasts own 32-h slice into every cluster CTA's
// double-buffered hT; sync = one barrier.cluster per step. Phase A (own k-chunk of
// next step) runs between arrive and wait to hide barrier + DSMEM drain.
__global__ void __launch_bounds__(512, 1) __cluster_dims__(8, 1, 1)
lstm_kernel(const int* __restrict__ len) {
    extern __shared__ float smem[];
    float* sWT = smem;                     // [128][260]
    float* hT0 = smem + 128 * 260;         // [16][260]
    float* hT1 = hT0 + 16 * 260;           // [16][260]
    float* pre = hT1 + 16 * 260;           // [32][132]

    int gx  = blockIdx.x;   // gate tile == cluster rank
    int gy  = blockIdx.y;
    int dir = blockIdx.z;
    int tid = threadIdx.x;
    int b0  = gy * 16;
    int g0  = gx * 128;     // reordered row base
    int h0  = gx * 32;      // h-index base == own k-chunk base
    int own0 = h0;
    int nloc = len[b0];     // sorted descending -> tile max

    // resident weights
    const float* WTT = &g_WTT[((size_t)dir * G4 + g0) * 256];
    for (int e = tid; e < 128 * 256; e += 512) {
        int row = e >> 8, k = e & 255;
        sWT[row * 260 + k] = WTT[e];
    }
    for (int e = tid; e < 2 * 16 * 260; e += 512) hT0[e] = 0.0f;
    __syncthreads();

    int tx = tid & 127;          // local gate row
    int q  = tid >> 7;
    int ty = q & 1;              // batch half
    int kz = q >> 1;             // k half

    // epilogue cell ownership (fixed across steps)
    int hl = tid & 31, b2 = tid >> 5;
    int bme = b0 + b2;
    int mylen = len[bme];
    float c_reg = 0.0f, h_reg = 0.0f;

    // precompute remote DSMEM addresses for the broadcast target cell
    unsigned int rem_addr[8];
    {
        float* dst0 = &hT0[b2 * 260 + h0 + hl];
        unsigned int lcl;
        asm("{ .reg .u64 t; cvta.to.shared.u64 t, %1; cvt.u32.u64 %0, t; }"
            : "=r"(lcl) : "l"(dst0));
        #pragma unroll
        for (int r = 0; r < 8; r++) {
            unsigned int ra;
            asm("mapa.shared::cluster.u32 %0, %1, %2;" : "=r"(ra) : "r"(lcl), "r"(r));
            rem_addr[r] = ra;
        }
    }
    const unsigned int buf_off = 16 * 260 * 4;  // bytes between hT0 and hT1

    // phase-B hole bounds (uniform per CTA)
    int lo = kz * 128;
    int segA_end = lo + 128, segB_beg = lo + 128;
    if (own0 >= lo && own0 < lo + 128) { segA_end = own0; segB_beg = own0 + 32; }

    // all cluster CTAs' smem initialized before any DSMEM writes
    asm volatile("barrier.cluster.arrive.aligned;" ::: "memory");
    asm volatile("barrier.cluster.wait.aligned;"   ::: "memory");

    unsigned long long acc[8];
    #pragma unroll
    for (int j = 0; j < 8; j++) acc[j] = 0ULL;   // phase A of step 0 (h=0)

    for (int i = 0; i < nloc; i++) {
        int cur = i & 1;
        float* hC = cur ? hT1 : hT0;
        float* hN = cur ? hT0 : hT1;
        int s = dir ? (nloc - 1 - i) : i;

        // xp prefetch (kz==0 threads add xp)
        float xpre[8];
        if (kz == 0) {
            size_t xb = (((size_t)dir * T + s) * B + b0 + ty * 8) * G4 + g0 + tx;
            #pragma unroll
            for (int j = 0; j < 8; j++) xpre[j] = g_xp[xb + (size_t)j * G4];
        }

        // ---- phase B: k in [lo,segA_end) u [segB_beg, lo+128) over hC ----
        {
            const float* wrow  = &sWT[tx * 260];
            const float* hbase = &hC[(ty * 8) * 260];
            #pragma unroll 4
            for (int k = lo; k < segA_end; k += 4) {
                ulonglong2 w2 = *(const ulonglong2*)(wrow + k);
                #pragma unroll
                for (int j = 0; j < 8; j++) {
                    ulonglong2 h2 = *(const ulonglong2*)(hbase + j * 260 + k);
                    ffma2(acc[j], w2.x, h2.x);
                    ffma2(acc[j], w2.y, h2.y);
                }
            }
            #pragma unroll 4
            for (int k = segB_beg; k < lo + 128; k += 4) {
                ulonglong2 w2 = *(const ulonglong2*)(wrow + k);
                #pragma unroll
                for (int j = 0; j < 8; j++) {
                    ulonglong2 h2 = *(const ulonglong2*)(hbase + j * 260 + k);
                    ffma2(acc[j], w2.x, h2.x);
                    ffma2(acc[j], w2.y, h2.y);
                }
            }
        }
        #pragma unroll
        for (int j = 0; j < 8; j++) {
            float2 f2 = *reinterpret_cast<float2*>(&acc[j]);
            float v = f2.x + f2.y;
            if (kz == 0) v += xpre[j];
            pre[(kz * 16 + ty * 8 + j) * 132 + tx] = v;
        }
        __syncthreads();

        // ---- epilogue: own cell (c,h in regs), then DSMEM broadcast ----
        if (s < mylen) {
            float4 gA = *(const float4*)&pre[b2 * 132 + 4 * hl];
            float4 gB = *(const float4*)&pre[(16 + b2) * 132 + 4 * hl];
            float gi = gA.x + gB.x, gf = gA.y + gB.y;
            float gg = gA.z + gB.z, go = gA.w + gB.w;
            float cn = sigmoid_fast(gf) * c_reg + sigmoid_fast(gi) * tanh_fast(gg);
            h_reg = sigmoid_fast(go) * tanh_fast(cn);
            c_reg = cn;
            g_hstore[(((size_t)dir * T + s) * B + bme) * H + h0 + hl] = h_reg;
        }
        {
            unsigned int boff = cur ? 0u : buf_off;  // hN buffer offset from hT0
            hN[b2 * 260 + h0 + hl] = h_reg;          // own rank: plain store
            #pragma unroll
            for (int r = 0; r < 8; r++) {
                if (r == gx) continue;
                asm volatile("st.shared::cluster.f32 [%0], %1;"
                             :: "r"(rem_addr[r] + boff), "f"(h_reg) : "memory");
            }
        }
        __syncthreads();
        asm volatile("barrier.cluster.arrive.aligned;" ::: "memory");

        // ---- phase A for next step: own k-chunk over hN (own slice local) ----
        #pragma unroll
        for (int j = 0; j < 8; j++) acc[j] = 0ULL;
        if (i + 1 < nloc) {
            const float* wrow  = &sWT[tx * 260];
            const float* hbase = &hN[(ty * 8) * 260];
            int ka = own0 + kz * 16;
            #pragma unroll
            for (int kk = 0; kk < 16; kk += 4) {
                ulonglong2 w2 = *(const ulonglong2*)(wrow + ka + kk);
                #pragma unroll
                for (int j = 0; j < 8; j++) {
                    ulonglong2 h2 = *(const ulonglong2*)(hbase + j * 260 + ka + kk);
                    ffma2(acc[j], w2.x, h2.x);
                    ffma2(acc[j], w2.y, h2.y);
                }
            }
        }
        asm volatile("barrier.cluster.wait.aligned;" ::: "memory");
    }
}

// ------------------- scores: comb_W . tanh(out_W @ [hf;hb] + addr_feat) -------------------
__global__ void __launch_bounds__(256) score_kernel(const int* __restrict__ len,
                                                    const float* __restrict__ comb_W) {
    int b = blockIdx.y;
    int t0 = blockIdx.x * 8;
    int n = len[b];
    if (t0 >= n) return;
    int w = threadIdx.x >> 5, lane = threadIdx.x & 31;
    int t = t0 + w;
    if (t >= n) return;
    float a0 = g_af[b * 32 + lane], a1 = 0.f, a2 = 0.f, a3 = 0.f;
    const float* hf = &g_hstore[(((size_t)0 * T + t) * B + b) * H];
    const float* hb = &g_hstore[(((size_t)1 * T + t) * B + b) * H];
    #pragma unroll 8
    for (int k = 0; k < 256; k += 4) {
        float4 h4 = *(const float4*)&hf[k];
        a0 = fmaf(g_outWT[(k + 0) * 32 + lane], h4.x, a0);
        a1 = fmaf(g_outWT[(k + 1) * 32 + lane], h4.y, a1);
        a2 = fmaf(g_outWT[(k + 2) * 32 + lane], h4.z, a2);
        a3 = fmaf(g_outWT[(k + 3) * 32 + lane], h4.w, a3);
    }
    #pragma unroll 8
    for (int k = 0; k < 256; k += 4) {
        float4 h4 = *(const float4*)&hb[k];
        a0 = fmaf(g_outWT[(256 + k + 0) * 32 + lane], h4.x, a0);
        a1 = fmaf(g_outWT[(256 + k + 1) * 32 + lane], h4.y, a1);
        a2 = fmaf(g_outWT[(256 + k + 2) * 32 + lane], h4.z, a2);
        a3 = fmaf(g_outWT[(256 + k + 3) * 32 + lane], h4.w, a3);
    }
    float v = tanhf(a0 + a1 + a2 + a3) * comb_W[lane];
    #pragma unroll
    for (int off = 16; off; off >>= 1) v += __shfl_down_sync(0xffffffffu, v, off);
    if (lane == 0) g_scores[b * T + t] = v;
}

// ------------------- masked log-softmax over T -------------------
__global__ void __launch_bounds__(256) softmax_kernel(const int* __restrict__ len,
                                                      float* __restrict__ out) {
    int b = blockIdx.x;
    int n = len[b];
    int tid = threadIdx.x;
    __shared__ float red[256];
    float m = -1e30f;
    for (int t = tid; t < n; t += 256) m = fmaxf(m, g_scores[b * T + t]);
    red[tid] = m; __syncthreads();
    for (int st = 128; st; st >>= 1) {
        if (tid < st) red[tid] = fmaxf(red[tid], red[tid + st]);
        __syncthreads();
    }
    m = red[0]; __syncthreads();
    float sum = 0.f;
    for (int t = tid; t < n; t += 256) sum += expf(g_scores[b * T + t] - m);
    red[tid] = sum; __syncthreads();
    for (int st = 128; st; st >>= 1) {
        if (tid < st) red[tid] += red[tid + st];
        __syncthreads();
    }
    float lse = m + logf(red[0]);
    for (int t = tid; t < T; t += 256)
        out[b * T + t] = (t < n) ? (g_scores[b * T + t] - lse) : 0.0f;
}

// ------------------- launch -------------------
extern "C" void kernel_launch(void* const* d_in, const int* in_sizes, int n_in,
                              void* d_out, int out_size) {
    (void)in_sizes; (void)n_in; (void)out_size;
    const float* addr      = (const float*)d_in[0];
    const int*   addr_type = (const int*)  d_in[1];
    const float* loc_dense = (const float*)d_in[2];
    const float* time_dist = (const float*)d_in[3];
    const int*   len       = (const int*)  d_in[4];
    const float* poi_emb   = (const float*)d_in[5];
    const float* time_W    = (const float*)d_in[6];
    const float* time_b    = (const float*)d_in[7];
    const float* addr_W    = (const float*)d_in[8];
    const float* addr_b    = (const float*)d_in[9];
    const float* Wih_f     = (const float*)d_in[10];
    const float* Whh_f     = (const float*)d_in[11];
    const float* b_f       = (const float*)d_in[12];
    const float* Wih_b     = (const float*)d_in[13];
    const float* Whh_b     = (const float*)d_in[14];
    const float* b_b       = (const float*)d_in[15];
    const float* out_W     = (const float*)d_in[16];
    const float* comb_W    = (const float*)d_in[17];
    float* out = (float*)d_out;

    static int smem_set = 0;
    const int LSTM_SMEM = (128 * 260 + 2 * 16 * 260 + 32 * 132) * 4;  // 183296 B
    if (!smem_set) {
        cudaFuncSetAttribute(lstm_kernel,
                             cudaFuncAttributeMaxDynamicSharedMemorySize, LSTM_SMEM);
        smem_set = 1;
    }

    addr_kernel<<<1, 128>>>(addr, addr_type, poi_emb, addr_W, addr_b);
    prep_kernel<<<2048, 256>>>(Whh_f, Whh_b, out_W);
    xp_kernel<<<dim3(32, 128, 2), 256>>>(loc_dense, time_dist, len, time_W, time_b,
                                         Wih_f, b_f, Wih_b, b_b);
    lstm_kernel<<<dim3(8, 8, 2), 512, LSTM_SMEM>>>(len);
    score_kernel<<<dim3(128, 128), 256>>>(len, comb_W);
    softmax_kernel<<<128, 256>>>(len, out);
}